// round 8
// baseline (speedup 1.0000x reference)
#include <cuda_runtime.h>
#include <cuda_bf16.h>
#include <math.h>
#include <stdint.h>

#define D_MODEL 512
#define D_FF    2048
#define GKN     8
#define NTOK    4096

// K-concat layouts:
//  layer1 activations: [bases(4096) | Sh(512) | Sh(512) | Sl(512)]  strideK=5632
//  layer1 weights:     [Ws  (4096)  | Wbh(512)| Wbl(512)| Wbh(512)]
//  layer2 activations: [bases(16384)| Sh(2048)| Sh(2048)| Sl(2048)] strideK=22528
#define K1P (D_MODEL * GKN + 3 * D_MODEL)   // 5632
#define K2P (D_FF * GKN + 3 * D_FF)         // 22528

__device__ __nv_bfloat16 g_A1[(size_t)NTOK * K1P];
__device__ __nv_bfloat16 g_A2[(size_t)NTOK * K2P];
__device__ __nv_bfloat16 g_W1[(size_t)D_FF * K1P];
__device__ __nv_bfloat16 g_W2[(size_t)D_MODEL * K2P];

// ---------------------------------------------------------------------------
// PTX helpers (arch-agnostic on .target sm_103)
// ---------------------------------------------------------------------------
__device__ __forceinline__ uint32_t cvta_smem(const void* p) {
    uint32_t a;
    asm("{ .reg .u64 t; cvta.to.shared.u64 t, %1; cvt.u32.u64 %0, t; }" : "=r"(a) : "l"(p));
    return a;
}
__device__ __forceinline__ void cp16(uint32_t s, const void* g) {
    asm volatile("cp.async.cg.shared.global [%0], [%1], 16;" :: "r"(s), "l"(g));
}
__device__ __forceinline__ void cp_commit() {
    asm volatile("cp.async.commit_group;" ::: "memory");
}
template <int N>
__device__ __forceinline__ void cp_wait() {
    asm volatile("cp.async.wait_group %0;" :: "n"(N) : "memory");
}
__device__ __forceinline__ void ldmx4(uint32_t* r, uint32_t a) {
    asm volatile("ldmatrix.sync.aligned.m8n8.x4.shared.b16 {%0,%1,%2,%3}, [%4];"
                 : "=r"(r[0]), "=r"(r[1]), "=r"(r[2]), "=r"(r[3]) : "r"(a));
}
__device__ __forceinline__ void mma16816(float* d, const uint32_t* a, uint32_t b0, uint32_t b1) {
    asm volatile(
        "mma.sync.aligned.m16n8k16.row.col.f32.bf16.bf16.f32 "
        "{%0,%1,%2,%3}, {%4,%5,%6,%7}, {%8,%9}, {%0,%1,%2,%3};"
        : "+f"(d[0]), "+f"(d[1]), "+f"(d[2]), "+f"(d[3])
        : "r"(a[0]), "r"(a[1]), "r"(a[2]), "r"(a[3]), "r"(b0), "r"(b1));
}

// ---------------------------------------------------------------------------
// KAN expansion core: given fp32 v + knots, produce sh, sl, packed bases.
// ---------------------------------------------------------------------------
struct KanExp {
    __nv_bfloat16 sh, sl;
    uint4 pk;
};
__device__ __forceinline__ KanExp kan_expand(float v, const float* t, float ih) {
    KanExp r;
    float s = v * __fdividef(1.0f, 1.0f + __expf(-v));
    r.sh = __float2bfloat16(s);
    r.sl = __float2bfloat16(s - __bfloat162float(r.sh));

    float b[11];
#pragma unroll
    for (int j = 0; j < 11; j++) b[j] = (v >= t[j] && v < t[j + 1]) ? 1.0f : 0.0f;

    const float w1 = ih, w2 = ih * 0.5f, w3 = ih * (1.0f / 3.0f);
#pragma unroll
    for (int q = 0; q < 10; q++)
        b[q] = ((v - t[q]) * b[q] + (t[q + 2] - v) * b[q + 1]) * w1;
#pragma unroll
    for (int q = 0; q < 9; q++)
        b[q] = ((v - t[q]) * b[q] + (t[q + 3] - v) * b[q + 1]) * w2;
#pragma unroll
    for (int q = 0; q < 8; q++)
        b[q] = ((v - t[q]) * b[q] + (t[q + 4] - v) * b[q + 1]) * w3;

    __nv_bfloat162 p0 = __floats2bfloat162_rn(b[0], b[1]);
    __nv_bfloat162 p1 = __floats2bfloat162_rn(b[2], b[3]);
    __nv_bfloat162 p2 = __floats2bfloat162_rn(b[4], b[5]);
    __nv_bfloat162 p3 = __floats2bfloat162_rn(b[6], b[7]);
    r.pk.x = *(uint32_t*)&p0; r.pk.y = *(uint32_t*)&p1;
    r.pk.z = *(uint32_t*)&p2; r.pk.w = *(uint32_t*)&p3;
    return r;
}

// ---------------------------------------------------------------------------
// Layer-1 input expansion into packed K-concat activation buffer A1.
// ---------------------------------------------------------------------------
__global__ void expand_pack(const float* __restrict__ x,
                            const float* __restrict__ grid,
                            __nv_bfloat16* __restrict__ pA,
                            int total, int in_log2, int strideK) {
    int idx = blockIdx.x * blockDim.x + threadIdx.x;
    if (idx >= total) return;
    const int IN = 1 << in_log2;
    const int row = idx >> in_log2;
    const int i = idx & (IN - 1);

    float t[12];
#pragma unroll
    for (int j = 0; j < 12; j++) t[j] = __ldg(grid + j);
    float ih = __fdividef(1.0f, t[1] - t[0]);

    KanExp e = kan_expand(x[idx], t, ih);

    __nv_bfloat16* rowp = pA + (size_t)row * strideK;
    *(uint4*)(rowp + i * 8) = e.pk;
    const int off = IN * 8;
    rowp[off + i]          = e.sh;
    rowp[off + IN + i]     = e.sh;
    rowp[off + 2 * IN + i] = e.sl;
}

// ---------------------------------------------------------------------------
// Weight packing: [Ws | Wbh | Wbl | Wbh]
// ---------------------------------------------------------------------------
__global__ void pack_w(const float* __restrict__ wb,
                       const float* __restrict__ ws,
                       __nv_bfloat16* __restrict__ pW,
                       int total, int in_log2, int strideK) {
    int idx = blockIdx.x * blockDim.x + threadIdx.x;
    if (idx >= total) return;
    const int IN = 1 << in_log2;
    const int o = idx >> in_log2;
    const int i = idx & (IN - 1);

    float base = wb[idx];
    __nv_bfloat16 hi = __float2bfloat16(base);
    __nv_bfloat16 lo = __float2bfloat16(base - __bfloat162float(hi));

    float4 s0 = ((const float4*)ws)[idx * 2];
    float4 s1 = ((const float4*)ws)[idx * 2 + 1];
    __nv_bfloat162 p0 = __floats2bfloat162_rn(s0.x, s0.y);
    __nv_bfloat162 p1 = __floats2bfloat162_rn(s0.z, s0.w);
    __nv_bfloat162 p2 = __floats2bfloat162_rn(s1.x, s1.y);
    __nv_bfloat162 p3 = __floats2bfloat162_rn(s1.z, s1.w);
    uint4 pk;
    pk.x = *(uint32_t*)&p0; pk.y = *(uint32_t*)&p1;
    pk.z = *(uint32_t*)&p2; pk.w = *(uint32_t*)&p3;

    __nv_bfloat16* rowp = pW + (size_t)o * strideK;
    *(uint4*)(rowp + i * 8) = pk;
    const int off = IN * 8;
    rowp[off + i]          = hi;
    rowp[off + IN + i]     = lo;
    rowp[off + 2 * IN + i] = hi;
}

// ---------------------------------------------------------------------------
// bf16 mma.sync GEMM: C(M,Nout) = A(M,K) * B(Nout,K)^T, fp32 accumulate.
// 4 warps (2x2), warp tile (MI*16) x (NI*8). BK=64, 3-stage cp.async,
// one __syncthreads per K-iter, fragment double-buffering.
// KAN=true: fused epilogue — treat acc as h, expand silu+bases, write A2
//           (layer-2 packed activations) instead of C.
// ---------------------------------------------------------------------------
#define BKK 64
#define STAGES 3
#define LDT 72

template <int MI, int NI, bool KAN>
__global__ void __launch_bounds__(128, 2)
gemm_mma(const __nv_bfloat16* __restrict__ A, const __nv_bfloat16* __restrict__ B,
         float* __restrict__ C, __nv_bfloat16* __restrict__ A2,
         const float* __restrict__ grid, int Nout, int K) {
    constexpr int BM_ = 2 * MI * 16;
    constexpr int BN_ = 2 * NI * 8;
    constexpr int TILE_A = BM_ * LDT;
    constexpr int TILE_B = BN_ * LDT;
    extern __shared__ __nv_bfloat16 sm[];
    const uint32_t sm_base = cvta_smem(sm);

    const int tid = threadIdx.x;
    const int lane = tid & 31;
    const int wid = tid >> 5;
    const int wm = wid >> 1;
    const int wn = wid & 1;
    const int m0 = blockIdx.y * BM_;
    const int n0 = blockIdx.x * BN_;

    const __nv_bfloat16* Ag = A + (size_t)m0 * K;
    const __nv_bfloat16* Bg = B + (size_t)n0 * K;

    const int lrow = tid >> 3;
    const int lcol = (tid & 7) * 8;

    const int nk = K / BKK;

    auto stage_load = [&](int ks) {
        const int buf = ks % STAGES;
        const size_t koff = (size_t)ks * BKK + lcol;
        const uint32_t abase = sm_base + (uint32_t)(buf * (TILE_A + TILE_B)) * 2;
        const uint32_t bbase = abase + (uint32_t)TILE_A * 2;
#pragma unroll
        for (int r = 0; r < BM_; r += 16)
            cp16(abase + (uint32_t)((lrow + r) * LDT + lcol) * 2,
                 Ag + (size_t)(lrow + r) * K + koff);
#pragma unroll
        for (int r = 0; r < BN_; r += 16)
            cp16(bbase + (uint32_t)((lrow + r) * LDT + lcol) * 2,
                 Bg + (size_t)(lrow + r) * K + koff);
        cp_commit();
    };

    float acc[MI][NI][4];
#pragma unroll
    for (int i = 0; i < MI; i++)
#pragma unroll
        for (int j = 0; j < NI; j++)
#pragma unroll
            for (int e = 0; e < 4; e++) acc[i][j][e] = 0.0f;

    const int lm_row = lane & 15;
    const int lm_koff = (lane >> 4) * 8;

    uint32_t afr[2][MI][4];
    uint32_t bfr[2][NI / 2][4];

    stage_load(0);
    stage_load(1);

    for (int ks = 0; ks < nk; ks++) {
        if (ks + 1 < nk) cp_wait<1>(); else cp_wait<0>();
        __syncthreads();
        if (ks + 2 < nk) stage_load(ks + 2);

        const int buf = ks % STAGES;
        const uint32_t abase = sm_base + (uint32_t)(buf * (TILE_A + TILE_B)) * 2 +
                               (uint32_t)((wm * MI * 16 + lm_row) * LDT + lm_koff) * 2;
        const uint32_t bbase = sm_base + (uint32_t)(buf * (TILE_A + TILE_B) + TILE_A) * 2 +
                               (uint32_t)((wn * NI * 8 + lm_row) * LDT + lm_koff) * 2;

#pragma unroll
        for (int mi = 0; mi < MI; mi++)
            ldmx4(afr[0][mi], abase + (uint32_t)(mi * 16 * LDT) * 2);
#pragma unroll
        for (int g = 0; g < NI / 2; g++)
            ldmx4(bfr[0][g], bbase + (uint32_t)(g * 16 * LDT) * 2);

#pragma unroll
        for (int kf = 0; kf < 4; kf++) {
            const int cur = kf & 1, nxt = cur ^ 1;
            if (kf < 3) {
                const uint32_t ka = abase + (uint32_t)((kf + 1) * 16) * 2;
                const uint32_t kb = bbase + (uint32_t)((kf + 1) * 16) * 2;
#pragma unroll
                for (int mi = 0; mi < MI; mi++)
                    ldmx4(afr[nxt][mi], ka + (uint32_t)(mi * 16 * LDT) * 2);
#pragma unroll
                for (int g = 0; g < NI / 2; g++)
                    ldmx4(bfr[nxt][g], kb + (uint32_t)(g * 16 * LDT) * 2);
            }
#pragma unroll
            for (int mi = 0; mi < MI; mi++)
#pragma unroll
                for (int ni = 0; ni < NI; ni++) {
                    const int g = ni >> 1, o = ni & 1;
                    mma16816(acc[mi][ni], afr[cur][mi], bfr[cur][g][o], bfr[cur][g][o + 2]);
                }
        }
    }

    const int erow = lane >> 2;
    const int ecol = (lane & 3) * 2;

    if (KAN) {
        // fused layer-2 expansion: acc IS h; write packed A2 rows
        float t[12];
#pragma unroll
        for (int j = 0; j < 12; j++) t[j] = __ldg(grid + j);
        const float ih = __fdividef(1.0f, t[1] - t[0]);

#pragma unroll
        for (int mi = 0; mi < MI; mi++) {
#pragma unroll
            for (int ni = 0; ni < NI; ni++) {
#pragma unroll
                for (int e = 0; e < 4; e++) {
                    const int row = m0 + wm * MI * 16 + mi * 16 + erow + ((e >> 1) ? 8 : 0);
                    const int col = n0 + wn * NI * 8 + ni * 8 + ecol + (e & 1);
                    KanExp ex = kan_expand(acc[mi][ni][e], t, ih);
                    __nv_bfloat16* rowp = A2 + (size_t)row * K2P;
                    *(uint4*)(rowp + col * 8) = ex.pk;
                    rowp[D_FF * 8 + col]            = ex.sh;
                    rowp[D_FF * 8 + D_FF + col]     = ex.sh;
                    rowp[D_FF * 8 + 2 * D_FF + col] = ex.sl;
                }
            }
        }
    } else {
#pragma unroll
        for (int mi = 0; mi < MI; mi++) {
#pragma unroll
            for (int ni = 0; ni < NI; ni++) {
                const int row = m0 + wm * MI * 16 + mi * 16 + erow;
                const int col = n0 + wn * NI * 8 + ni * 8 + ecol;
                float* p0 = C + (size_t)row * Nout + col;
                float* p1 = C + (size_t)(row + 8) * Nout + col;
                *(float2*)p0 = make_float2(acc[mi][ni][0], acc[mi][ni][1]);
                *(float2*)p1 = make_float2(acc[mi][ni][2], acc[mi][ni][3]);
            }
        }
    }
}

// ---------------------------------------------------------------------------
// Launch
// ---------------------------------------------------------------------------
extern "C" void kernel_launch(void* const* d_in, const int* in_sizes, int n_in,
                              void* d_out, int out_size) {
    const float* x    = (const float*)d_in[0];
    const float* grid = (const float*)d_in[1];
    const float* w1b  = (const float*)d_in[2];
    const float* w1s  = (const float*)d_in[3];
    const float* w2b  = (const float*)d_in[4];
    const float* w2s  = (const float*)d_in[5];
    float* out = (float*)d_out;

    const int ntok = in_sizes[0] / D_MODEL;  // 4096

    __nv_bfloat16 *A1, *A2, *W1, *W2;
    cudaGetSymbolAddress((void**)&A1, g_A1);
    cudaGetSymbolAddress((void**)&A2, g_A2);
    cudaGetSymbolAddress((void**)&W1, g_W1);
    cudaGetSymbolAddress((void**)&W2, g_W2);

    const int smem1 = STAGES * (128 + 128) * LDT * 2;  // 110592
    const int smem2 = STAGES * (128 + 64) * LDT * 2;   //  82944
    cudaFuncSetAttribute((const void*)gemm_mma<4, 8, true>,
                         cudaFuncAttributeMaxDynamicSharedMemorySize, smem1);
    cudaFuncSetAttribute((const void*)gemm_mma<4, 4, false>,
                         cudaFuncAttributeMaxDynamicSharedMemorySize, smem2);

    // pack weights
    {
        int n1 = D_FF * D_MODEL;
        pack_w<<<(n1 + 255) / 256, 256>>>(w1b, w1s, W1, n1, 9, K1P);
        int n2 = D_MODEL * D_FF;
        pack_w<<<(n2 + 255) / 256, 256>>>(w2b, w2s, W2, n2, 11, K2P);
    }

    // ---- layer 1 input expansion ----
    const int tot1 = ntok * D_MODEL;
    expand_pack<<<(tot1 + 255) / 256, 256>>>(x, grid, A1, tot1, 9, K1P);

    // ---- layer 1 GEMM with fused layer-2 expansion epilogue ----
    dim3 grid1(D_FF / 128, ntok / 128);
    gemm_mma<4, 8, true><<<grid1, 128, smem1>>>(A1, W1, nullptr, A2, grid, D_FF, K1P);

    // ---- layer 2 GEMM ----
    dim3 grid2(D_MODEL / 64, ntok / 128);
    gemm_mma<4, 4, false><<<grid2, 128, smem2>>>(A2, W2, out, nullptr, nullptr, D_MODEL, K2P);
}

// round 9
// speedup vs baseline: 1.1715x; 1.1715x over previous
#include <cuda_runtime.h>
#include <cuda_bf16.h>
#include <math.h>
#include <stdint.h>

#define D_MODEL 512
#define D_FF    2048
#define GKN     8
#define NTOK    4096

// K-concat layouts:
//  layer1 activations: [bases(4096) | Sh(512) | Sh(512) | Sl(512)]  strideK=5632
//  layer1 weights:     [Ws  (4096)  | Wbh(512)| Wbl(512)| Wbh(512)]
//  layer2 activations: [bases(16384)| Sh(2048)| Sh(2048)| Sl(2048)] strideK=22528
#define K1P (D_MODEL * GKN + 3 * D_MODEL)   // 5632
#define K2P (D_FF * GKN + 3 * D_FF)         // 22528

__device__ __nv_bfloat16 g_A1[(size_t)NTOK * K1P];
__device__ __nv_bfloat16 g_A2[(size_t)NTOK * K2P];
__device__ __nv_bfloat16 g_W1[(size_t)D_FF * K1P];
__device__ __nv_bfloat16 g_W2[(size_t)D_MODEL * K2P];
__device__ float         g_H [(size_t)NTOK * D_FF];

// ---------------------------------------------------------------------------
// PTX helpers (arch-agnostic on .target sm_103)
// ---------------------------------------------------------------------------
__device__ __forceinline__ uint32_t cvta_smem(const void* p) {
    uint32_t a;
    asm("{ .reg .u64 t; cvta.to.shared.u64 t, %1; cvt.u32.u64 %0, t; }" : "=r"(a) : "l"(p));
    return a;
}
__device__ __forceinline__ void cp16(uint32_t s, const void* g) {
    asm volatile("cp.async.cg.shared.global [%0], [%1], 16;" :: "r"(s), "l"(g));
}
__device__ __forceinline__ void cp_commit() {
    asm volatile("cp.async.commit_group;" ::: "memory");
}
template <int N>
__device__ __forceinline__ void cp_wait() {
    asm volatile("cp.async.wait_group %0;" :: "n"(N) : "memory");
}
__device__ __forceinline__ void ldmx4(uint32_t* r, uint32_t a) {
    asm volatile("ldmatrix.sync.aligned.m8n8.x4.shared.b16 {%0,%1,%2,%3}, [%4];"
                 : "=r"(r[0]), "=r"(r[1]), "=r"(r[2]), "=r"(r[3]) : "r"(a));
}
__device__ __forceinline__ void mma16816(float* d, const uint32_t* a, uint32_t b0, uint32_t b1) {
    asm volatile(
        "mma.sync.aligned.m16n8k16.row.col.f32.bf16.bf16.f32 "
        "{%0,%1,%2,%3}, {%4,%5,%6,%7}, {%8,%9}, {%0,%1,%2,%3};"
        : "+f"(d[0]), "+f"(d[1]), "+f"(d[2]), "+f"(d[3])
        : "r"(a[0]), "r"(a[1]), "r"(a[2]), "r"(a[3]), "r"(b0), "r"(b1));
}

// ---------------------------------------------------------------------------
// Expansion into packed K-concat activation buffer.
// ---------------------------------------------------------------------------
__global__ void expand_pack(const float* __restrict__ x,
                            const float* __restrict__ grid,
                            __nv_bfloat16* __restrict__ pA,
                            int total, int in_log2, int strideK) {
    int idx = blockIdx.x * blockDim.x + threadIdx.x;
    if (idx >= total) return;
    const int IN = 1 << in_log2;
    const int row = idx >> in_log2;
    const int i = idx & (IN - 1);

    float v = x[idx];
    float s = v * __fdividef(1.0f, 1.0f + __expf(-v));
    __nv_bfloat16 sh = __float2bfloat16(s);
    __nv_bfloat16 sl = __float2bfloat16(s - __bfloat162float(sh));

    float t[12];
#pragma unroll
    for (int j = 0; j < 12; j++) t[j] = __ldg(grid + j);
    float ih = __fdividef(1.0f, t[1] - t[0]);

    float b[11];
#pragma unroll
    for (int j = 0; j < 11; j++) b[j] = (v >= t[j] && v < t[j + 1]) ? 1.0f : 0.0f;

    const float w1 = ih, w2 = ih * 0.5f, w3 = ih * (1.0f / 3.0f);
#pragma unroll
    for (int q = 0; q < 10; q++)
        b[q] = ((v - t[q]) * b[q] + (t[q + 2] - v) * b[q + 1]) * w1;
#pragma unroll
    for (int q = 0; q < 9; q++)
        b[q] = ((v - t[q]) * b[q] + (t[q + 3] - v) * b[q + 1]) * w2;
#pragma unroll
    for (int q = 0; q < 8; q++)
        b[q] = ((v - t[q]) * b[q] + (t[q + 4] - v) * b[q + 1]) * w3;

    __nv_bfloat162 p0 = __floats2bfloat162_rn(b[0], b[1]);
    __nv_bfloat162 p1 = __floats2bfloat162_rn(b[2], b[3]);
    __nv_bfloat162 p2 = __floats2bfloat162_rn(b[4], b[5]);
    __nv_bfloat162 p3 = __floats2bfloat162_rn(b[6], b[7]);
    uint4 pk;
    pk.x = *(uint32_t*)&p0; pk.y = *(uint32_t*)&p1;
    pk.z = *(uint32_t*)&p2; pk.w = *(uint32_t*)&p3;

    __nv_bfloat16* rowp = pA + (size_t)row * strideK;
    *(uint4*)(rowp + i * 8) = pk;
    const int off = IN * 8;
    rowp[off + i]          = sh;
    rowp[off + IN + i]     = sh;
    rowp[off + 2 * IN + i] = sl;
}

// ---------------------------------------------------------------------------
// Weight packing: [Ws | Wbh | Wbl | Wbh]
// ---------------------------------------------------------------------------
__global__ void pack_w(const float* __restrict__ wb,
                       const float* __restrict__ ws,
                       __nv_bfloat16* __restrict__ pW,
                       int total, int in_log2, int strideK) {
    int idx = blockIdx.x * blockDim.x + threadIdx.x;
    if (idx >= total) return;
    const int IN = 1 << in_log2;
    const int o = idx >> in_log2;
    const int i = idx & (IN - 1);

    float base = wb[idx];
    __nv_bfloat16 hi = __float2bfloat16(base);
    __nv_bfloat16 lo = __float2bfloat16(base - __bfloat162float(hi));

    float4 s0 = ((const float4*)ws)[idx * 2];
    float4 s1 = ((const float4*)ws)[idx * 2 + 1];
    __nv_bfloat162 p0 = __floats2bfloat162_rn(s0.x, s0.y);
    __nv_bfloat162 p1 = __floats2bfloat162_rn(s0.z, s0.w);
    __nv_bfloat162 p2 = __floats2bfloat162_rn(s1.x, s1.y);
    __nv_bfloat162 p3 = __floats2bfloat162_rn(s1.z, s1.w);
    uint4 pk;
    pk.x = *(uint32_t*)&p0; pk.y = *(uint32_t*)&p1;
    pk.z = *(uint32_t*)&p2; pk.w = *(uint32_t*)&p3;

    __nv_bfloat16* rowp = pW + (size_t)o * strideK;
    *(uint4*)(rowp + i * 8) = pk;
    const int off = IN * 8;
    rowp[off + i]          = hi;
    rowp[off + IN + i]     = lo;
    rowp[off + 2 * IN + i] = hi;
}

// ---------------------------------------------------------------------------
// bf16 mma.sync GEMM: C(M,Nout) = A(M,K) * B(Nout,K)^T, fp32 accumulate.
// 4 warps (2x2), warp tile (MI*16) x (NI*8). BK=64, 3-stage cp.async,
// one __syncthreads per K-iter, fragment double-buffering.
// OCC = target CTAs/SM (register budget hint).
// ---------------------------------------------------------------------------
#define BKK 64
#define STAGES 3
#define LDT 72

template <int MI, int NI, int OCC>
__global__ void __launch_bounds__(128, OCC)
gemm_mma(const __nv_bfloat16* __restrict__ A, const __nv_bfloat16* __restrict__ B,
         float* __restrict__ C, int Nout, int K) {
    constexpr int BM_ = 2 * MI * 16;
    constexpr int BN_ = 2 * NI * 8;
    constexpr int TILE_A = BM_ * LDT;
    constexpr int TILE_B = BN_ * LDT;
    extern __shared__ __nv_bfloat16 sm[];
    const uint32_t sm_base = cvta_smem(sm);

    const int tid = threadIdx.x;
    const int lane = tid & 31;
    const int wid = tid >> 5;
    const int wm = wid >> 1;
    const int wn = wid & 1;
    const int m0 = blockIdx.y * BM_;
    const int n0 = blockIdx.x * BN_;

    const __nv_bfloat16* Ag = A + (size_t)m0 * K;
    const __nv_bfloat16* Bg = B + (size_t)n0 * K;

    // loader: 8 threads per 64-elem row (16B each); 128 threads = 16 rows/pass
    const int lrow = tid >> 3;
    const int lcol = (tid & 7) * 8;

    const int nk = K / BKK;

    auto stage_load = [&](int ks) {
        const int buf = ks % STAGES;
        const size_t koff = (size_t)ks * BKK + lcol;
        const uint32_t abase = sm_base + (uint32_t)(buf * (TILE_A + TILE_B)) * 2;
        const uint32_t bbase = abase + (uint32_t)TILE_A * 2;
#pragma unroll
        for (int r = 0; r < BM_; r += 16)
            cp16(abase + (uint32_t)((lrow + r) * LDT + lcol) * 2,
                 Ag + (size_t)(lrow + r) * K + koff);
#pragma unroll
        for (int r = 0; r < BN_; r += 16)
            cp16(bbase + (uint32_t)((lrow + r) * LDT + lcol) * 2,
                 Bg + (size_t)(lrow + r) * K + koff);
        cp_commit();
    };

    float acc[MI][NI][4];
#pragma unroll
    for (int i = 0; i < MI; i++)
#pragma unroll
        for (int j = 0; j < NI; j++)
#pragma unroll
            for (int e = 0; e < 4; e++) acc[i][j][e] = 0.0f;

    const int lm_row = lane & 15;
    const int lm_koff = (lane >> 4) * 8;

    // double-buffered fragments
    uint32_t afr[2][MI][4];
    uint32_t bfr[2][NI / 2][4];

    stage_load(0);
    stage_load(1);

    for (int ks = 0; ks < nk; ks++) {
        if (ks + 1 < nk) cp_wait<1>(); else cp_wait<0>();
        __syncthreads();
        if (ks + 2 < nk) stage_load(ks + 2);

        const int buf = ks % STAGES;
        const uint32_t abase = sm_base + (uint32_t)(buf * (TILE_A + TILE_B)) * 2 +
                               (uint32_t)((wm * MI * 16 + lm_row) * LDT + lm_koff) * 2;
        const uint32_t bbase = sm_base + (uint32_t)(buf * (TILE_A + TILE_B) + TILE_A) * 2 +
                               (uint32_t)((wn * NI * 8 + lm_row) * LDT + lm_koff) * 2;

        // preload phase 0 fragments
#pragma unroll
        for (int mi = 0; mi < MI; mi++)
            ldmx4(afr[0][mi], abase + (uint32_t)(mi * 16 * LDT) * 2);
#pragma unroll
        for (int g = 0; g < NI / 2; g++)
            ldmx4(bfr[0][g], bbase + (uint32_t)(g * 16 * LDT) * 2);

#pragma unroll
        for (int kf = 0; kf < 4; kf++) {
            const int cur = kf & 1, nxt = cur ^ 1;
            if (kf < 3) {
                const uint32_t ka = abase + (uint32_t)((kf + 1) * 16) * 2;
                const uint32_t kb = bbase + (uint32_t)((kf + 1) * 16) * 2;
#pragma unroll
                for (int mi = 0; mi < MI; mi++)
                    ldmx4(afr[nxt][mi], ka + (uint32_t)(mi * 16 * LDT) * 2);
#pragma unroll
                for (int g = 0; g < NI / 2; g++)
                    ldmx4(bfr[nxt][g], kb + (uint32_t)(g * 16 * LDT) * 2);
            }
#pragma unroll
            for (int mi = 0; mi < MI; mi++)
#pragma unroll
                for (int ni = 0; ni < NI; ni++) {
                    const int g = ni >> 1, o = ni & 1;
                    mma16816(acc[mi][ni], afr[cur][mi], bfr[cur][g][o], bfr[cur][g][o + 2]);
                }
        }
    }

    // epilogue
    const int erow = lane >> 2;
    const int ecol = (lane & 3) * 2;
#pragma unroll
    for (int mi = 0; mi < MI; mi++) {
#pragma unroll
        for (int ni = 0; ni < NI; ni++) {
            const int row = m0 + wm * MI * 16 + mi * 16 + erow;
            const int col = n0 + wn * NI * 8 + ni * 8 + ecol;
            float* p0 = C + (size_t)row * Nout + col;
            float* p1 = C + (size_t)(row + 8) * Nout + col;
            *(float2*)p0 = make_float2(acc[mi][ni][0], acc[mi][ni][1]);
            *(float2*)p1 = make_float2(acc[mi][ni][2], acc[mi][ni][3]);
        }
    }
}

// ---------------------------------------------------------------------------
// Launch
// ---------------------------------------------------------------------------
extern "C" void kernel_launch(void* const* d_in, const int* in_sizes, int n_in,
                              void* d_out, int out_size) {
    const float* x    = (const float*)d_in[0];
    const float* grid = (const float*)d_in[1];
    const float* w1b  = (const float*)d_in[2];
    const float* w1s  = (const float*)d_in[3];
    const float* w2b  = (const float*)d_in[4];
    const float* w2s  = (const float*)d_in[5];
    float* out = (float*)d_out;

    const int ntok = in_sizes[0] / D_MODEL;  // 4096

    __nv_bfloat16 *A1, *A2, *W1, *W2;
    float* H;
    cudaGetSymbolAddress((void**)&A1, g_A1);
    cudaGetSymbolAddress((void**)&A2, g_A2);
    cudaGetSymbolAddress((void**)&W1, g_W1);
    cudaGetSymbolAddress((void**)&W2, g_W2);
    cudaGetSymbolAddress((void**)&H,  g_H);

    // layer1: warp tile 64x64 -> BM=128, BN=128; 2 CTAs/SM
    // layer2: warp tile 32x32 -> BM=64,  BN=64;  4 CTAs/SM, 512 CTAs (full wave)
    const int smem1 = STAGES * (128 + 128) * LDT * 2;  // 110592
    const int smem2 = STAGES * (64 + 64) * LDT * 2;    //  55296
    cudaFuncSetAttribute((const void*)gemm_mma<4, 8, 2>,
                         cudaFuncAttributeMaxDynamicSharedMemorySize, smem1);
    cudaFuncSetAttribute((const void*)gemm_mma<2, 4, 4>,
                         cudaFuncAttributeMaxDynamicSharedMemorySize, smem2);

    // pack weights
    {
        int n1 = D_FF * D_MODEL;
        pack_w<<<(n1 + 255) / 256, 256>>>(w1b, w1s, W1, n1, 9, K1P);
        int n2 = D_MODEL * D_FF;
        pack_w<<<(n2 + 255) / 256, 256>>>(w2b, w2s, W2, n2, 11, K2P);
    }

    // ---- layer 1 ----
    const int tot1 = ntok * D_MODEL;
    expand_pack<<<(tot1 + 255) / 256, 256>>>(x, grid, A1, tot1, 9, K1P);

    dim3 grid1(D_FF / 128, ntok / 128);
    gemm_mma<4, 8, 2><<<grid1, 128, smem1>>>(A1, W1, H, D_FF, K1P);

    // ---- layer 2 ----
    const int tot2 = ntok * D_FF;
    expand_pack<<<(tot2 + 255) / 256, 256>>>(H, grid, A2, tot2, 11, K2P);

    dim3 grid2(D_MODEL / 64, ntok / 64);
    gemm_mma<2, 4, 4><<<grid2, 128, smem2>>>(A2, W2, out, D_MODEL, K2P);
}

// round 10
// speedup vs baseline: 1.1898x; 1.0156x over previous
#include <cuda_runtime.h>
#include <cuda_bf16.h>
#include <math.h>
#include <stdint.h>

#define D_MODEL 512
#define D_FF    2048
#define GKN     8
#define NTOK    4096

// K-concat layouts:
//  layer1 activations: [bases(4096) | Sh(512) | Sh(512) | Sl(512)]  strideK=5632
//  layer1 weights:     [Ws  (4096)  | Wbh(512)| Wbl(512)| Wbh(512)]
//  layer2 activations: [bases(16384)| Sh(2048)| Sh(2048)| Sl(2048)] strideK=22528
#define K1P (D_MODEL * GKN + 3 * D_MODEL)   // 5632
#define K2P (D_FF * GKN + 3 * D_FF)         // 22528

__device__ __nv_bfloat16 g_A1[(size_t)NTOK * K1P];
__device__ __nv_bfloat16 g_A2[(size_t)NTOK * K2P];
__device__ __nv_bfloat16 g_W1[(size_t)D_FF * K1P];
__device__ __nv_bfloat16 g_W2[(size_t)D_MODEL * K2P];
__device__ float         g_H [(size_t)NTOK * D_FF];

// ---------------------------------------------------------------------------
// PTX helpers (arch-agnostic on .target sm_103)
// ---------------------------------------------------------------------------
__device__ __forceinline__ uint32_t cvta_smem(const void* p) {
    uint32_t a;
    asm("{ .reg .u64 t; cvta.to.shared.u64 t, %1; cvt.u32.u64 %0, t; }" : "=r"(a) : "l"(p));
    return a;
}
__device__ __forceinline__ void cp16(uint32_t s, const void* g) {
    asm volatile("cp.async.cg.shared.global [%0], [%1], 16;" :: "r"(s), "l"(g));
}
__device__ __forceinline__ void cp_commit() {
    asm volatile("cp.async.commit_group;" ::: "memory");
}
template <int N>
__device__ __forceinline__ void cp_wait() {
    asm volatile("cp.async.wait_group %0;" :: "n"(N) : "memory");
}
__device__ __forceinline__ void ldmx4(uint32_t* r, uint32_t a) {
    asm volatile("ldmatrix.sync.aligned.m8n8.x4.shared.b16 {%0,%1,%2,%3}, [%4];"
                 : "=r"(r[0]), "=r"(r[1]), "=r"(r[2]), "=r"(r[3]) : "r"(a));
}
__device__ __forceinline__ void mma16816(float* d, const uint32_t* a, uint32_t b0, uint32_t b1) {
    asm volatile(
        "mma.sync.aligned.m16n8k16.row.col.f32.bf16.bf16.f32 "
        "{%0,%1,%2,%3}, {%4,%5,%6,%7}, {%8,%9}, {%0,%1,%2,%3};"
        : "+f"(d[0]), "+f"(d[1]), "+f"(d[2]), "+f"(d[3])
        : "r"(a[0]), "r"(a[1]), "r"(a[2]), "r"(a[3]), "r"(b0), "r"(b1));
}

// ---------------------------------------------------------------------------
// Closed-form uniform cubic B-spline expansion.
// s=(v-t0)*ih, j0=floor(s), w=s-j0. Nonzero bases (cardinal N3 translates):
//   b[j0]   = w^3/6
//   b[j0-1] = (1+3w+3w^2-3w^3)/6
//   b[j0-2] = (4-6w^2+3w^3)/6
//   b[j0-3] = (1-w)^3/6
// clipped to output range 0..7; all-zero outside domain (matches half-open
// order-0 intervals of the reference recursion).
// ---------------------------------------------------------------------------
__device__ __forceinline__ void expand_one(float v, float t0, float ih,
                                           __nv_bfloat16& sh, __nv_bfloat16& sl,
                                           uint4& pk) {
    float s = v * __fdividef(1.0f, 1.0f + __expf(-v));
    sh = __float2bfloat16(s);
    sl = __float2bfloat16(s - __bfloat162float(sh));

    float u = (v - t0) * ih;
    float jf = floorf(u);
    int j0 = (int)jf;
    float w = u - jf;
    float w2 = w * w, w3 = w2 * w;
    const float k6 = 1.0f / 6.0f;
    float c3 = w3 * k6;                                     // q = j0
    float c2 = k6 * (1.0f + 3.0f * w + 3.0f * w2 - 3.0f * w3); // q = j0-1
    float c1 = k6 * (4.0f - 6.0f * w2 + 3.0f * w3);            // q = j0-2
    float c0 = k6 * (1.0f - 3.0f * w + 3.0f * w2 - w3);        // q = j0-3

    float bq[8];
#pragma unroll
    for (int q = 0; q < 8; q++) {
        int d = j0 - q;
        float val = 0.0f;
        val = (d == 0) ? c3 : val;
        val = (d == 1) ? c2 : val;
        val = (d == 2) ? c1 : val;
        val = (d == 3) ? c0 : val;
        bq[q] = val;
    }

    __nv_bfloat162 p0 = __floats2bfloat162_rn(bq[0], bq[1]);
    __nv_bfloat162 p1 = __floats2bfloat162_rn(bq[2], bq[3]);
    __nv_bfloat162 p2 = __floats2bfloat162_rn(bq[4], bq[5]);
    __nv_bfloat162 p3 = __floats2bfloat162_rn(bq[6], bq[7]);
    pk.x = *(uint32_t*)&p0; pk.y = *(uint32_t*)&p1;
    pk.z = *(uint32_t*)&p2; pk.w = *(uint32_t*)&p3;
}

// ---------------------------------------------------------------------------
// Expansion into packed K-concat activation buffer.
// ---------------------------------------------------------------------------
__global__ void expand_pack(const float* __restrict__ x,
                            const float* __restrict__ grid,
                            __nv_bfloat16* __restrict__ pA,
                            int total, int in_log2, int strideK) {
    int idx = blockIdx.x * blockDim.x + threadIdx.x;
    if (idx >= total) return;
    const int IN = 1 << in_log2;
    const int row = idx >> in_log2;
    const int i = idx & (IN - 1);

    const float t0 = __ldg(grid);
    const float ih = __fdividef(1.0f, __ldg(grid + 1) - t0);

    __nv_bfloat16 sh, sl;
    uint4 pk;
    expand_one(x[idx], t0, ih, sh, sl, pk);

    __nv_bfloat16* rowp = pA + (size_t)row * strideK;
    *(uint4*)(rowp + i * 8) = pk;
    const int off = IN * 8;
    rowp[off + i]          = sh;
    rowp[off + IN + i]     = sh;
    rowp[off + 2 * IN + i] = sl;
}

// ---------------------------------------------------------------------------
// Weight packing: [Ws | Wbh | Wbl | Wbh]
// ---------------------------------------------------------------------------
__global__ void pack_w(const float* __restrict__ wb,
                       const float* __restrict__ ws,
                       __nv_bfloat16* __restrict__ pW,
                       int total, int in_log2, int strideK) {
    int idx = blockIdx.x * blockDim.x + threadIdx.x;
    if (idx >= total) return;
    const int IN = 1 << in_log2;
    const int o = idx >> in_log2;
    const int i = idx & (IN - 1);

    float base = wb[idx];
    __nv_bfloat16 hi = __float2bfloat16(base);
    __nv_bfloat16 lo = __float2bfloat16(base - __bfloat162float(hi));

    float4 s0 = ((const float4*)ws)[idx * 2];
    float4 s1 = ((const float4*)ws)[idx * 2 + 1];
    __nv_bfloat162 p0 = __floats2bfloat162_rn(s0.x, s0.y);
    __nv_bfloat162 p1 = __floats2bfloat162_rn(s0.z, s0.w);
    __nv_bfloat162 p2 = __floats2bfloat162_rn(s1.x, s1.y);
    __nv_bfloat162 p3 = __floats2bfloat162_rn(s1.z, s1.w);
    uint4 pk;
    pk.x = *(uint32_t*)&p0; pk.y = *(uint32_t*)&p1;
    pk.z = *(uint32_t*)&p2; pk.w = *(uint32_t*)&p3;

    __nv_bfloat16* rowp = pW + (size_t)o * strideK;
    *(uint4*)(rowp + i * 8) = pk;
    const int off = IN * 8;
    rowp[off + i]          = hi;
    rowp[off + IN + i]     = lo;
    rowp[off + 2 * IN + i] = hi;
}

// ---------------------------------------------------------------------------
// bf16 mma.sync GEMM: C(M,Nout) = A(M,K) * B(Nout,K)^T, fp32 accumulate.
// 4 warps (2x2), warp tile (MI*16) x (NI*8). BK=64, 3-stage cp.async,
// one __syncthreads per K-iter, fragment double-buffering.
// ---------------------------------------------------------------------------
#define BKK 64
#define STAGES 3
#define LDT 72

template <int MI, int NI, int OCC>
__global__ void __launch_bounds__(128, OCC)
gemm_mma(const __nv_bfloat16* __restrict__ A, const __nv_bfloat16* __restrict__ B,
         float* __restrict__ C, int Nout, int K) {
    constexpr int BM_ = 2 * MI * 16;
    constexpr int BN_ = 2 * NI * 8;
    constexpr int TILE_A = BM_ * LDT;
    constexpr int TILE_B = BN_ * LDT;
    extern __shared__ __nv_bfloat16 sm[];
    const uint32_t sm_base = cvta_smem(sm);

    const int tid = threadIdx.x;
    const int lane = tid & 31;
    const int wid = tid >> 5;
    const int wm = wid >> 1;
    const int wn = wid & 1;
    const int m0 = blockIdx.y * BM_;
    const int n0 = blockIdx.x * BN_;

    const __nv_bfloat16* Ag = A + (size_t)m0 * K;
    const __nv_bfloat16* Bg = B + (size_t)n0 * K;

    const int lrow = tid >> 3;
    const int lcol = (tid & 7) * 8;

    const int nk = K / BKK;

    auto stage_load = [&](int ks) {
        const int buf = ks % STAGES;
        const size_t koff = (size_t)ks * BKK + lcol;
        const uint32_t abase = sm_base + (uint32_t)(buf * (TILE_A + TILE_B)) * 2;
        const uint32_t bbase = abase + (uint32_t)TILE_A * 2;
#pragma unroll
        for (int r = 0; r < BM_; r += 16)
            cp16(abase + (uint32_t)((lrow + r) * LDT + lcol) * 2,
                 Ag + (size_t)(lrow + r) * K + koff);
#pragma unroll
        for (int r = 0; r < BN_; r += 16)
            cp16(bbase + (uint32_t)((lrow + r) * LDT + lcol) * 2,
                 Bg + (size_t)(lrow + r) * K + koff);
        cp_commit();
    };

    float acc[MI][NI][4];
#pragma unroll
    for (int i = 0; i < MI; i++)
#pragma unroll
        for (int j = 0; j < NI; j++)
#pragma unroll
            for (int e = 0; e < 4; e++) acc[i][j][e] = 0.0f;

    const int lm_row = lane & 15;
    const int lm_koff = (lane >> 4) * 8;

    uint32_t afr[2][MI][4];
    uint32_t bfr[2][NI / 2][4];

    stage_load(0);
    stage_load(1);

    for (int ks = 0; ks < nk; ks++) {
        if (ks + 1 < nk) cp_wait<1>(); else cp_wait<0>();
        __syncthreads();
        if (ks + 2 < nk) stage_load(ks + 2);

        const int buf = ks % STAGES;
        const uint32_t abase = sm_base + (uint32_t)(buf * (TILE_A + TILE_B)) * 2 +
                               (uint32_t)((wm * MI * 16 + lm_row) * LDT + lm_koff) * 2;
        const uint32_t bbase = sm_base + (uint32_t)(buf * (TILE_A + TILE_B) + TILE_A) * 2 +
                               (uint32_t)((wn * NI * 8 + lm_row) * LDT + lm_koff) * 2;

#pragma unroll
        for (int mi = 0; mi < MI; mi++)
            ldmx4(afr[0][mi], abase + (uint32_t)(mi * 16 * LDT) * 2);
#pragma unroll
        for (int g = 0; g < NI / 2; g++)
            ldmx4(bfr[0][g], bbase + (uint32_t)(g * 16 * LDT) * 2);

#pragma unroll
        for (int kf = 0; kf < 4; kf++) {
            const int cur = kf & 1, nxt = cur ^ 1;
            if (kf < 3) {
                const uint32_t ka = abase + (uint32_t)((kf + 1) * 16) * 2;
                const uint32_t kb = bbase + (uint32_t)((kf + 1) * 16) * 2;
#pragma unroll
                for (int mi = 0; mi < MI; mi++)
                    ldmx4(afr[nxt][mi], ka + (uint32_t)(mi * 16 * LDT) * 2);
#pragma unroll
                for (int g = 0; g < NI / 2; g++)
                    ldmx4(bfr[nxt][g], kb + (uint32_t)(g * 16 * LDT) * 2);
            }
#pragma unroll
            for (int mi = 0; mi < MI; mi++)
#pragma unroll
                for (int ni = 0; ni < NI; ni++) {
                    const int g = ni >> 1, o = ni & 1;
                    mma16816(acc[mi][ni], afr[cur][mi], bfr[cur][g][o], bfr[cur][g][o + 2]);
                }
        }
    }

    // epilogue
    const int erow = lane >> 2;
    const int ecol = (lane & 3) * 2;
#pragma unroll
    for (int mi = 0; mi < MI; mi++) {
#pragma unroll
        for (int ni = 0; ni < NI; ni++) {
            const int row = m0 + wm * MI * 16 + mi * 16 + erow;
            const int col = n0 + wn * NI * 8 + ni * 8 + ecol;
            float* p0 = C + (size_t)row * Nout + col;
            float* p1 = C + (size_t)(row + 8) * Nout + col;
            *(float2*)p0 = make_float2(acc[mi][ni][0], acc[mi][ni][1]);
            *(float2*)p1 = make_float2(acc[mi][ni][2], acc[mi][ni][3]);
        }
    }
}

// ---------------------------------------------------------------------------
// Launch
// ---------------------------------------------------------------------------
extern "C" void kernel_launch(void* const* d_in, const int* in_sizes, int n_in,
                              void* d_out, int out_size) {
    const float* x    = (const float*)d_in[0];
    const float* grid = (const float*)d_in[1];
    const float* w1b  = (const float*)d_in[2];
    const float* w1s  = (const float*)d_in[3];
    const float* w2b  = (const float*)d_in[4];
    const float* w2s  = (const float*)d_in[5];
    float* out = (float*)d_out;

    const int ntok = in_sizes[0] / D_MODEL;  // 4096

    __nv_bfloat16 *A1, *A2, *W1, *W2;
    float* H;
    cudaGetSymbolAddress((void**)&A1, g_A1);
    cudaGetSymbolAddress((void**)&A2, g_A2);
    cudaGetSymbolAddress((void**)&W1, g_W1);
    cudaGetSymbolAddress((void**)&W2, g_W2);
    cudaGetSymbolAddress((void**)&H,  g_H);

    const int smem1 = STAGES * (128 + 128) * LDT * 2;  // 110592
    const int smem2 = STAGES * (64 + 64) * LDT * 2;    //  55296
    cudaFuncSetAttribute((const void*)gemm_mma<4, 8, 2>,
                         cudaFuncAttributeMaxDynamicSharedMemorySize, smem1);
    cudaFuncSetAttribute((const void*)gemm_mma<2, 4, 4>,
                         cudaFuncAttributeMaxDynamicSharedMemorySize, smem2);

    // pack weights
    {
        int n1 = D_FF * D_MODEL;
        pack_w<<<(n1 + 255) / 256, 256>>>(w1b, w1s, W1, n1, 9, K1P);
        int n2 = D_MODEL * D_FF;
        pack_w<<<(n2 + 255) / 256, 256>>>(w2b, w2s, W2, n2, 11, K2P);
    }

    // ---- layer 1 ----
    const int tot1 = ntok * D_MODEL;
    expand_pack<<<(tot1 + 255) / 256, 256>>>(x, grid, A1, tot1, 9, K1P);

    dim3 grid1(D_FF / 128, ntok / 128);
    gemm_mma<4, 8, 2><<<grid1, 128, smem1>>>(A1, W1, H, D_FF, K1P);

    // ---- layer 2 ----
    const int tot2 = ntok * D_FF;
    expand_pack<<<(tot2 + 255) / 256, 256>>>(H, grid, A2, tot2, 11, K2P);

    dim3 grid2(D_MODEL / 64, ntok / 64);
    gemm_mma<2, 4, 4><<<grid2, 128, smem2>>>(A2, W2, out, D_MODEL, K2P);
}

// round 11
// speedup vs baseline: 1.2075x; 1.0149x over previous
#include <cuda_runtime.h>
#include <cuda_bf16.h>
#include <math.h>
#include <stdint.h>

#define D_MODEL 512
#define D_FF    2048
#define GKN     8
#define NTOK    4096

// K-concat layouts:
//  layer1 activations: [bases(4096) | Sh(512) | Sh(512) | Sl(512)]  strideK=5632
//  layer1 weights:     [Ws  (4096)  | Wbh(512)| Wbl(512)| Wbh(512)]
//  layer2 activations: [bases(16384)| Sh(2048)| Sh(2048)| Sl(2048)] strideK=22528
#define K1P (D_MODEL * GKN + 3 * D_MODEL)   // 5632
#define K2P (D_FF * GKN + 3 * D_FF)         // 22528

__device__ __nv_bfloat16 g_A1[(size_t)NTOK * K1P];
__device__ __nv_bfloat16 g_A2[(size_t)NTOK * K2P];
__device__ __nv_bfloat16 g_W1[(size_t)D_FF * K1P];
__device__ __nv_bfloat16 g_W2[(size_t)D_MODEL * K2P];
__device__ float         g_H [(size_t)NTOK * D_FF];

// ---------------------------------------------------------------------------
// PTX helpers (arch-agnostic on .target sm_103)
// ---------------------------------------------------------------------------
__device__ __forceinline__ uint32_t cvta_smem(const void* p) {
    uint32_t a;
    asm("{ .reg .u64 t; cvta.to.shared.u64 t, %1; cvt.u32.u64 %0, t; }" : "=r"(a) : "l"(p));
    return a;
}
__device__ __forceinline__ void cp16(uint32_t s, const void* g) {
    asm volatile("cp.async.cg.shared.global [%0], [%1], 16;" :: "r"(s), "l"(g));
}
__device__ __forceinline__ void cp_commit() {
    asm volatile("cp.async.commit_group;" ::: "memory");
}
template <int N>
__device__ __forceinline__ void cp_wait() {
    asm volatile("cp.async.wait_group %0;" :: "n"(N) : "memory");
}
__device__ __forceinline__ void ldmx4(uint32_t* r, uint32_t a) {
    asm volatile("ldmatrix.sync.aligned.m8n8.x4.shared.b16 {%0,%1,%2,%3}, [%4];"
                 : "=r"(r[0]), "=r"(r[1]), "=r"(r[2]), "=r"(r[3]) : "r"(a));
}
__device__ __forceinline__ void mma16816(float* d, const uint32_t* a, uint32_t b0, uint32_t b1) {
    asm volatile(
        "mma.sync.aligned.m16n8k16.row.col.f32.bf16.bf16.f32 "
        "{%0,%1,%2,%3}, {%4,%5,%6,%7}, {%8,%9}, {%0,%1,%2,%3};"
        : "+f"(d[0]), "+f"(d[1]), "+f"(d[2]), "+f"(d[3])
        : "r"(a[0]), "r"(a[1]), "r"(a[2]), "r"(a[3]), "r"(b0), "r"(b1));
}

// ---------------------------------------------------------------------------
// Closed-form uniform cubic B-spline expansion (cardinal N3 translates).
// ---------------------------------------------------------------------------
__device__ __forceinline__ void expand_one(float v, float t0, float ih,
                                           __nv_bfloat16& sh, __nv_bfloat16& sl,
                                           uint4& pk) {
    float s = v * __fdividef(1.0f, 1.0f + __expf(-v));
    sh = __float2bfloat16(s);
    sl = __float2bfloat16(s - __bfloat162float(sh));

    float u = (v - t0) * ih;
    float jf = floorf(u);
    int j0 = (int)jf;
    float w = u - jf;
    float w2 = w * w, w3 = w2 * w;
    const float k6 = 1.0f / 6.0f;
    float c3 = w3 * k6;                                        // q = j0
    float c2 = k6 * (1.0f + 3.0f * w + 3.0f * w2 - 3.0f * w3); // q = j0-1
    float c1 = k6 * (4.0f - 6.0f * w2 + 3.0f * w3);            // q = j0-2
    float c0 = k6 * (1.0f - 3.0f * w + 3.0f * w2 - w3);        // q = j0-3

    float bq[8];
#pragma unroll
    for (int q = 0; q < 8; q++) {
        int d = j0 - q;
        float val = 0.0f;
        val = (d == 0) ? c3 : val;
        val = (d == 1) ? c2 : val;
        val = (d == 2) ? c1 : val;
        val = (d == 3) ? c0 : val;
        bq[q] = val;
    }

    __nv_bfloat162 p0 = __floats2bfloat162_rn(bq[0], bq[1]);
    __nv_bfloat162 p1 = __floats2bfloat162_rn(bq[2], bq[3]);
    __nv_bfloat162 p2 = __floats2bfloat162_rn(bq[4], bq[5]);
    __nv_bfloat162 p3 = __floats2bfloat162_rn(bq[6], bq[7]);
    pk.x = *(uint32_t*)&p0; pk.y = *(uint32_t*)&p1;
    pk.z = *(uint32_t*)&p2; pk.w = *(uint32_t*)&p3;
}

// ---------------------------------------------------------------------------
// Per-element job bodies
// ---------------------------------------------------------------------------
__device__ __forceinline__ void do_expand(const float* __restrict__ x,
                                          float t0, float ih,
                                          __nv_bfloat16* __restrict__ pA,
                                          int idx, int in_log2, int strideK) {
    const int IN = 1 << in_log2;
    const int row = idx >> in_log2;
    const int i = idx & (IN - 1);

    __nv_bfloat16 sh, sl;
    uint4 pk;
    expand_one(x[idx], t0, ih, sh, sl, pk);

    __nv_bfloat16* rowp = pA + (size_t)row * strideK;
    *(uint4*)(rowp + i * 8) = pk;
    const int off = IN * 8;
    rowp[off + i]          = sh;
    rowp[off + IN + i]     = sh;
    rowp[off + 2 * IN + i] = sl;
}

__device__ __forceinline__ void do_pack_w(const float* __restrict__ wb,
                                          const float* __restrict__ ws,
                                          __nv_bfloat16* __restrict__ pW,
                                          int idx, int in_log2, int strideK) {
    const int IN = 1 << in_log2;
    const int o = idx >> in_log2;
    const int i = idx & (IN - 1);

    float base = wb[idx];
    __nv_bfloat16 hi = __float2bfloat16(base);
    __nv_bfloat16 lo = __float2bfloat16(base - __bfloat162float(hi));

    float4 s0 = ((const float4*)ws)[idx * 2];
    float4 s1 = ((const float4*)ws)[idx * 2 + 1];
    __nv_bfloat162 p0 = __floats2bfloat162_rn(s0.x, s0.y);
    __nv_bfloat162 p1 = __floats2bfloat162_rn(s0.z, s0.w);
    __nv_bfloat162 p2 = __floats2bfloat162_rn(s1.x, s1.y);
    __nv_bfloat162 p3 = __floats2bfloat162_rn(s1.z, s1.w);
    uint4 pk;
    pk.x = *(uint32_t*)&p0; pk.y = *(uint32_t*)&p1;
    pk.z = *(uint32_t*)&p2; pk.w = *(uint32_t*)&p3;

    __nv_bfloat16* rowp = pW + (size_t)o * strideK;
    *(uint4*)(rowp + i * 8) = pk;
    const int off = IN * 8;
    rowp[off + i]          = hi;
    rowp[off + IN + i]     = lo;
    rowp[off + 2 * IN + i] = hi;
}

// ---------------------------------------------------------------------------
// Fused preprocessing: pack W1, pack W2, expand layer-1 input — one launch,
// grid partitioned by blockIdx.x. All three jobs are independent.
//   blocks [0, NB1)             : pack_w W1   (n = D_FF*D_MODEL)
//   blocks [NB1, NB1+NB2)       : pack_w W2   (n = D_MODEL*D_FF)
//   blocks [NB1+NB2, +NB3)      : expand x -> A1 (n = NTOK*D_MODEL)
// ---------------------------------------------------------------------------
#define NB1 (D_FF * D_MODEL / 256)           // 4096
#define NB2 (D_MODEL * D_FF / 256)           // 4096
#define NB3 (NTOK * D_MODEL / 256)           // 8192

__global__ void __launch_bounds__(256)
prep_kernel(const float* __restrict__ x, const float* __restrict__ grid,
            const float* __restrict__ w1b, const float* __restrict__ w1s,
            const float* __restrict__ w2b, const float* __restrict__ w2s,
            __nv_bfloat16* __restrict__ W1, __nv_bfloat16* __restrict__ W2,
            __nv_bfloat16* __restrict__ A1) {
    const int b = blockIdx.x;
    if (b < NB1) {
        int idx = b * 256 + threadIdx.x;
        do_pack_w(w1b, w1s, W1, idx, 9, K1P);
    } else if (b < NB1 + NB2) {
        int idx = (b - NB1) * 256 + threadIdx.x;
        do_pack_w(w2b, w2s, W2, idx, 11, K2P);
    } else {
        int idx = (b - NB1 - NB2) * 256 + threadIdx.x;
        const float t0 = __ldg(grid);
        const float ih = __fdividef(1.0f, __ldg(grid + 1) - t0);
        do_expand(x, t0, ih, A1, idx, 9, K1P);
    }
}

// ---------------------------------------------------------------------------
// Layer-2 expansion (depends on H from gemm1) — standalone.
// ---------------------------------------------------------------------------
__global__ void __launch_bounds__(256)
expand2_kernel(const float* __restrict__ h, const float* __restrict__ grid,
               __nv_bfloat16* __restrict__ A2, int total) {
    int idx = blockIdx.x * blockDim.x + threadIdx.x;
    if (idx >= total) return;
    const float t0 = __ldg(grid);
    const float ih = __fdividef(1.0f, __ldg(grid + 1) - t0);
    do_expand(h, t0, ih, A2, idx, 11, K2P);
}

// ---------------------------------------------------------------------------
// bf16 mma.sync GEMM: C(M,Nout) = A(M,K) * B(Nout,K)^T, fp32 accumulate.
// 4 warps (2x2), warp tile (MI*16) x (NI*8). BK=64, 3-stage cp.async,
// one __syncthreads per K-iter, fragment double-buffering.
// ---------------------------------------------------------------------------
#define BKK 64
#define STAGES 3
#define LDT 72

template <int MI, int NI, int OCC>
__global__ void __launch_bounds__(128, OCC)
gemm_mma(const __nv_bfloat16* __restrict__ A, const __nv_bfloat16* __restrict__ B,
         float* __restrict__ C, int Nout, int K) {
    constexpr int BM_ = 2 * MI * 16;
    constexpr int BN_ = 2 * NI * 8;
    constexpr int TILE_A = BM_ * LDT;
    constexpr int TILE_B = BN_ * LDT;
    extern __shared__ __nv_bfloat16 sm[];
    const uint32_t sm_base = cvta_smem(sm);

    const int tid = threadIdx.x;
    const int lane = tid & 31;
    const int wid = tid >> 5;
    const int wm = wid >> 1;
    const int wn = wid & 1;
    const int m0 = blockIdx.y * BM_;
    const int n0 = blockIdx.x * BN_;

    const __nv_bfloat16* Ag = A + (size_t)m0 * K;
    const __nv_bfloat16* Bg = B + (size_t)n0 * K;

    const int lrow = tid >> 3;
    const int lcol = (tid & 7) * 8;

    const int nk = K / BKK;

    auto stage_load = [&](int ks) {
        const int buf = ks % STAGES;
        const size_t koff = (size_t)ks * BKK + lcol;
        const uint32_t abase = sm_base + (uint32_t)(buf * (TILE_A + TILE_B)) * 2;
        const uint32_t bbase = abase + (uint32_t)TILE_A * 2;
#pragma unroll
        for (int r = 0; r < BM_; r += 16)
            cp16(abase + (uint32_t)((lrow + r) * LDT + lcol) * 2,
                 Ag + (size_t)(lrow + r) * K + koff);
#pragma unroll
        for (int r = 0; r < BN_; r += 16)
            cp16(bbase + (uint32_t)((lrow + r) * LDT + lcol) * 2,
                 Bg + (size_t)(lrow + r) * K + koff);
        cp_commit();
    };

    float acc[MI][NI][4];
#pragma unroll
    for (int i = 0; i < MI; i++)
#pragma unroll
        for (int j = 0; j < NI; j++)
#pragma unroll
            for (int e = 0; e < 4; e++) acc[i][j][e] = 0.0f;

    const int lm_row = lane & 15;
    const int lm_koff = (lane >> 4) * 8;

    uint32_t afr[2][MI][4];
    uint32_t bfr[2][NI / 2][4];

    stage_load(0);
    stage_load(1);

    for (int ks = 0; ks < nk; ks++) {
        if (ks + 1 < nk) cp_wait<1>(); else cp_wait<0>();
        __syncthreads();
        if (ks + 2 < nk) stage_load(ks + 2);

        const int buf = ks % STAGES;
        const uint32_t abase = sm_base + (uint32_t)(buf * (TILE_A + TILE_B)) * 2 +
                               (uint32_t)((wm * MI * 16 + lm_row) * LDT + lm_koff) * 2;
        const uint32_t bbase = sm_base + (uint32_t)(buf * (TILE_A + TILE_B) + TILE_A) * 2 +
                               (uint32_t)((wn * NI * 8 + lm_row) * LDT + lm_koff) * 2;

#pragma unroll
        for (int mi = 0; mi < MI; mi++)
            ldmx4(afr[0][mi], abase + (uint32_t)(mi * 16 * LDT) * 2);
#pragma unroll
        for (int g = 0; g < NI / 2; g++)
            ldmx4(bfr[0][g], bbase + (uint32_t)(g * 16 * LDT) * 2);

#pragma unroll
        for (int kf = 0; kf < 4; kf++) {
            const int cur = kf & 1, nxt = cur ^ 1;
            if (kf < 3) {
                const uint32_t ka = abase + (uint32_t)((kf + 1) * 16) * 2;
                const uint32_t kb = bbase + (uint32_t)((kf + 1) * 16) * 2;
#pragma unroll
                for (int mi = 0; mi < MI; mi++)
                    ldmx4(afr[nxt][mi], ka + (uint32_t)(mi * 16 * LDT) * 2);
#pragma unroll
                for (int g = 0; g < NI / 2; g++)
                    ldmx4(bfr[nxt][g], kb + (uint32_t)(g * 16 * LDT) * 2);
            }
#pragma unroll
            for (int mi = 0; mi < MI; mi++)
#pragma unroll
                for (int ni = 0; ni < NI; ni++) {
                    const int g = ni >> 1, o = ni & 1;
                    mma16816(acc[mi][ni], afr[cur][mi], bfr[cur][g][o], bfr[cur][g][o + 2]);
                }
        }
    }

    // epilogue
    const int erow = lane >> 2;
    const int ecol = (lane & 3) * 2;
#pragma unroll
    for (int mi = 0; mi < MI; mi++) {
#pragma unroll
        for (int ni = 0; ni < NI; ni++) {
            const int row = m0 + wm * MI * 16 + mi * 16 + erow;
            const int col = n0 + wn * NI * 8 + ni * 8 + ecol;
            float* p0 = C + (size_t)row * Nout + col;
            float* p1 = C + (size_t)(row + 8) * Nout + col;
            *(float2*)p0 = make_float2(acc[mi][ni][0], acc[mi][ni][1]);
            *(float2*)p1 = make_float2(acc[mi][ni][2], acc[mi][ni][3]);
        }
    }
}

// ---------------------------------------------------------------------------
// Launch
// ---------------------------------------------------------------------------
extern "C" void kernel_launch(void* const* d_in, const int* in_sizes, int n_in,
                              void* d_out, int out_size) {
    const float* x    = (const float*)d_in[0];
    const float* grid = (const float*)d_in[1];
    const float* w1b  = (const float*)d_in[2];
    const float* w1s  = (const float*)d_in[3];
    const float* w2b  = (const float*)d_in[4];
    const float* w2s  = (const float*)d_in[5];
    float* out = (float*)d_out;

    const int ntok = in_sizes[0] / D_MODEL;  // 4096

    __nv_bfloat16 *A1, *A2, *W1, *W2;
    float* H;
    cudaGetSymbolAddress((void**)&A1, g_A1);
    cudaGetSymbolAddress((void**)&A2, g_A2);
    cudaGetSymbolAddress((void**)&W1, g_W1);
    cudaGetSymbolAddress((void**)&W2, g_W2);
    cudaGetSymbolAddress((void**)&H,  g_H);

    const int smem1 = STAGES * (128 + 128) * LDT * 2;  // 110592
    const int smem2 = STAGES * (64 + 64) * LDT * 2;    //  55296
    cudaFuncSetAttribute((const void*)gemm_mma<4, 8, 2>,
                         cudaFuncAttributeMaxDynamicSharedMemorySize, smem1);
    cudaFuncSetAttribute((const void*)gemm_mma<2, 4, 4>,
                         cudaFuncAttributeMaxDynamicSharedMemorySize, smem2);

    // ---- fused preprocessing: pack W1, pack W2, expand layer-1 input ----
    prep_kernel<<<NB1 + NB2 + NB3, 256>>>(x, grid, w1b, w1s, w2b, w2s, W1, W2, A1);

    // ---- layer 1 GEMM ----
    dim3 grid1(D_FF / 128, ntok / 128);
    gemm_mma<4, 8, 2><<<grid1, 128, smem1>>>(A1, W1, H, D_FF, K1P);

    // ---- layer 2 expansion ----
    const int tot2 = ntok * D_FF;
    expand2_kernel<<<(tot2 + 255) / 256, 256>>>(H, grid, A2, tot2);

    // ---- layer 2 GEMM ----
    dim3 grid2(D_MODEL / 64, ntok / 64);
    gemm_mma<2, 4, 4><<<grid2, 128, smem2>>>(A2, W2, out, D_MODEL, K2P);
}